// round 2
// baseline (speedup 1.0000x reference)
#include <cuda_runtime.h>
#include <math.h>

#define NTHR   512
#define ROWS   128
#define HH     64
#define TENC   256
#define NIn    6
#define HSTR   65   // padded row stride for hidden state (odd -> conflict-free)

// ---- shared memory layout (floats) ----
// sWhh0 : 64*192 = 12288
// sWih1 : 12288
// sWhh1 : 12288
// sWih0 : 6*192 = 1152 (encoder) / first 192 = d_Wih0 vector (decoder)
// sB0i, sB0h, sB1i, sB1h : 192 each
// sH0 : 128*65 = 8320
// sH1 : 8320
// sX  : 128*7 = 896
// sPrev : 128
// sWon : 64, sWcv : 64, sHb : 2
#define SMEM_FLOATS (12288*3 + 1152 + 192*4 + 8320*2 + 896 + 128 + 64 + 64 + 2)

__device__ __forceinline__ void loadWT(float* dst, const float* __restrict__ g) {
    // g: [192][64] row-major -> dst: [64][192] with dst[k*192+j] = g[j*64+k]
    for (int i = threadIdx.x; i < 64 * 192; i += NTHR) {
        int k = i / 192, j = i - k * 192;
        dst[i] = g[j * 64 + k];
    }
}

// Accumulate hidden-state matmul: adds Hs @ Whh^T into aR/aZ/aHN for this
// thread's tile (2 rows x 8 units).
__device__ __forceinline__ void accum_h(const float* __restrict__ WT,
                                        const float* __restrict__ Hs,
                                        int r0, int jb,
                                        float aR[2][8], float aZ[2][8], float aHN[2][8]) {
    const float* h0p = Hs + r0 * HSTR;
    const float* h1p = h0p + HSTR;
    const float* w = WT + jb;
#pragma unroll 2
    for (int k = 0; k < HH; k++) {
        float hv0 = h0p[k], hv1 = h1p[k];
        float wr[8], wz[8], wn[8];
        *(float4*)&wr[0] = *(const float4*)(w);
        *(float4*)&wr[4] = *(const float4*)(w + 4);
        *(float4*)&wz[0] = *(const float4*)(w + 64);
        *(float4*)&wz[4] = *(const float4*)(w + 68);
        *(float4*)&wn[0] = *(const float4*)(w + 128);
        *(float4*)&wn[4] = *(const float4*)(w + 132);
#pragma unroll
        for (int u = 0; u < 8; u++) {
            aR[0][u]  = fmaf(hv0, wr[u], aR[0][u]);
            aR[1][u]  = fmaf(hv1, wr[u], aR[1][u]);
            aZ[0][u]  = fmaf(hv0, wz[u], aZ[0][u]);
            aZ[1][u]  = fmaf(hv1, wz[u], aZ[1][u]);
            aHN[0][u] = fmaf(hv0, wn[u], aHN[0][u]);
            aHN[1][u] = fmaf(hv1, wn[u], aHN[1][u]);
        }
        w += 192;
    }
}

// Accumulate input matmul: adds U @ Wih^T into aR/aZ/aIN.
template <int KU, int USTR>
__device__ __forceinline__ void accum_in(const float* __restrict__ U,
                                         const float* __restrict__ WT,
                                         int r0, int jb,
                                         float aR[2][8], float aZ[2][8], float aIN[2][8]) {
    const float* u0p = U + r0 * USTR;
    const float* u1p = u0p + USTR;
    const float* w = WT + jb;
#pragma unroll 2
    for (int k = 0; k < KU; k++) {
        float uv0 = u0p[k], uv1 = u1p[k];
        float wr[8], wz[8], wn[8];
        *(float4*)&wr[0] = *(const float4*)(w);
        *(float4*)&wr[4] = *(const float4*)(w + 4);
        *(float4*)&wz[0] = *(const float4*)(w + 64);
        *(float4*)&wz[4] = *(const float4*)(w + 68);
        *(float4*)&wn[0] = *(const float4*)(w + 128);
        *(float4*)&wn[4] = *(const float4*)(w + 132);
#pragma unroll
        for (int u = 0; u < 8; u++) {
            aR[0][u]  = fmaf(uv0, wr[u], aR[0][u]);
            aR[1][u]  = fmaf(uv1, wr[u], aR[1][u]);
            aZ[0][u]  = fmaf(uv0, wz[u], aZ[0][u]);
            aZ[1][u]  = fmaf(uv1, wz[u], aZ[1][u]);
            aIN[0][u] = fmaf(uv0, wn[u], aIN[0][u]);
            aIN[1][u] = fmaf(uv1, wn[u], aIN[1][u]);
        }
        w += 192;
    }
}

__device__ __forceinline__ void init_acc(const float* bi, const float* bh, int jb,
                                         float aR[2][8], float aZ[2][8],
                                         float aIN[2][8], float aHN[2][8]) {
#pragma unroll
    for (int u = 0; u < 8; u++) {
        float br = bi[jb + u] + bh[jb + u];
        float bz = bi[64 + jb + u] + bh[64 + jb + u];
        float bn_i = bi[128 + jb + u];
        float bn_h = bh[128 + jb + u];
        aR[0][u] = br;   aR[1][u] = br;
        aZ[0][u] = bz;   aZ[1][u] = bz;
        aIN[0][u] = bn_i; aIN[1][u] = bn_i;
        aHN[0][u] = bn_h; aHN[1][u] = bn_h;
    }
}

// GRU elementwise update. Contains the two required barriers:
// all reads of Hs precede the first sync; writes happen between syncs.
__device__ __forceinline__ void elt_update(float* Hs, int r0, int jb,
                                           float aR[2][8], float aZ[2][8],
                                           float aIN[2][8], float aHN[2][8]) {
    float hn[2][8];
#pragma unroll
    for (int i = 0; i < 2; i++) {
#pragma unroll
        for (int u = 0; u < 8; u++) {
            float r = 1.0f / (1.0f + expf(-aR[i][u]));
            float z = 1.0f / (1.0f + expf(-aZ[i][u]));
            float n = tanhf(fmaf(r, aHN[i][u], aIN[i][u]));
            float hold = Hs[(r0 + i) * HSTR + jb + u];
            hn[i][u] = fmaf(z, hold - n, n);   // (1-z)*n + z*h
        }
    }
    __syncthreads();
#pragma unroll
    for (int i = 0; i < 2; i++)
#pragma unroll
        for (int u = 0; u < 8; u++)
            Hs[(r0 + i) * HSTR + jb + u] = hn[i][u];
    __syncthreads();
}

extern "C" __global__ void __launch_bounds__(NTHR, 1)
ccseq_kernel(const float* __restrict__ x, const int* __restrict__ p_tlen,
             const float* eWih0, const float* eWhh0, const float* ebih0, const float* ebhh0,
             const float* eWih1, const float* eWhh1, const float* ebih1, const float* ebhh1,
             const float* dWih0, const float* dWhh0, const float* dbih0, const float* dbhh0,
             const float* dWih1, const float* dWhh1, const float* dbih1, const float* dbhh1,
             const float* Won, const float* bon, const float* Wcv, const float* bcv,
             float* __restrict__ out) {
    extern __shared__ float sm[];
    float* sWhh0 = sm;                  // 12288
    float* sWih1 = sWhh0 + 12288;       // 12288
    float* sWhh1 = sWih1 + 12288;       // 12288
    float* sWih0 = sWhh1 + 12288;       // 1152
    float* sB0i  = sWih0 + 1152;        // 192
    float* sB0h  = sB0i + 192;          // 192
    float* sB1i  = sB0h + 192;          // 192
    float* sB1h  = sB1i + 192;          // 192
    float* sH0   = sB1h + 192;          // 8320
    float* sH1   = sH0 + 8320;          // 8320
    float* sX    = sH1 + 8320;          // 896  [128][7]
    float* sPrev = sX + 896;            // 128
    float* sWon  = sPrev + 128;         // 64
    float* sWcv  = sWon + 64;           // 64
    float* sHb   = sWcv + 64;           // 2

    const int tid = threadIdx.x;
    const int rowbase = blockIdx.x * ROWS;
    const int ug = tid & 7;
    const int rg = tid >> 3;
    const int r0 = rg * 2;
    const int jb = ug * 8;

    // ---- load encoder weights (transposed) + biases, zero state ----
    loadWT(sWhh0, eWhh0);
    loadWT(sWih1, eWih1);
    loadWT(sWhh1, eWhh1);
    for (int i = tid; i < NIn * 192; i += NTHR) {
        int k = i / 192, j = i - k * 192;
        sWih0[i] = eWih0[j * NIn + k];
    }
    for (int i = tid; i < 192; i += NTHR) {
        sB0i[i] = ebih0[i];
        sB0h[i] = ebhh0[i];
        sB1i[i] = ebih1[i];
        sB1h[i] = ebhh1[i];
    }
    for (int i = tid; i < 2 * 8320; i += NTHR) sH0[i] = 0.0f;
    __syncthreads();

    const int TL = p_tlen[0];

    float aR[2][8], aZ[2][8], aIN[2][8], aHN[2][8];

    // ================= encoder =================
    for (int t = 0; t < TENC; t++) {
        // stage x[:, t, :] for this block's rows
        for (int i = tid; i < ROWS * NIn; i += NTHR) {
            int r = i / NIn, c = i - r * NIn;
            sX[r * 7 + c] = x[(rowbase + r) * (TENC * NIn) + t * NIn + c];
        }
        __syncthreads();

        // layer 0
        init_acc(sB0i, sB0h, jb, aR, aZ, aIN, aHN);
        accum_in<NIn, 7>(sX, sWih0, r0, jb, aR, aZ, aIN);
        accum_h(sWhh0, sH0, r0, jb, aR, aZ, aHN);
        elt_update(sH0, r0, jb, aR, aZ, aIN, aHN);

        // layer 1 (input = new h0)
        init_acc(sB1i, sB1h, jb, aR, aZ, aIN, aHN);
        accum_in<HH, HSTR>(sH0, sWih1, r0, jb, aR, aZ, aIN);
        accum_h(sWhh1, sH1, r0, jb, aR, aZ, aHN);
        elt_update(sH1, r0, jb, aR, aZ, aIN, aHN);
    }

    // ---- swap in decoder weights ----
    loadWT(sWhh0, dWhh0);
    loadWT(sWih1, dWih1);
    loadWT(sWhh1, dWhh1);
    for (int i = tid; i < 192; i += NTHR) {
        sWih0[i] = dWih0[i];     // [192,1] vector
        sB0i[i] = dbih0[i];
        sB0h[i] = dbhh0[i];
        sB1i[i] = dbih1[i];
        sB1h[i] = dbhh1[i];
    }
    for (int i = tid; i < HH; i += NTHR) {
        sWon[i] = Won[i];
        sWcv[i] = Wcv[i];
    }
    if (tid == 0) { sHb[0] = bon[0]; sHb[1] = bcv[0]; }
    for (int i = tid; i < ROWS; i += NTHR) sPrev[i] = 0.0f;
    __syncthreads();

    // ================= decoder =================
    for (int t = 0; t < TL; t++) {
        // layer 0: input = prev scalar
        init_acc(sB0i, sB0h, jb, aR, aZ, aIN, aHN);
        {
            float p0 = sPrev[r0], p1 = sPrev[r0 + 1];
#pragma unroll
            for (int u = 0; u < 8; u++) {
                float wr = sWih0[jb + u];
                float wz = sWih0[64 + jb + u];
                float wn = sWih0[128 + jb + u];
                aR[0][u]  = fmaf(p0, wr, aR[0][u]);
                aR[1][u]  = fmaf(p1, wr, aR[1][u]);
                aZ[0][u]  = fmaf(p0, wz, aZ[0][u]);
                aZ[1][u]  = fmaf(p1, wz, aZ[1][u]);
                aIN[0][u] = fmaf(p0, wn, aIN[0][u]);
                aIN[1][u] = fmaf(p1, wn, aIN[1][u]);
            }
        }
        accum_h(sWhh0, sH0, r0, jb, aR, aZ, aHN);
        elt_update(sH0, r0, jb, aR, aZ, aIN, aHN);

        // layer 1
        init_acc(sB1i, sB1h, jb, aR, aZ, aIN, aHN);
        accum_in<HH, HSTR>(sH0, sWih1, r0, jb, aR, aZ, aIN);
        accum_h(sWhh1, sH1, r0, jb, aR, aZ, aHN);
        elt_update(sH1, r0, jb, aR, aZ, aIN, aHN);

        // heads: logit/cv per row, hard gate, feed back + write out
        if (tid < ROWS) {
            const float* h = &sH1[tid * HSTR];
            float lg = sHb[0], cv = sHb[1];
#pragma unroll
            for (int j = 0; j < HH; j++) {
                lg = fmaf(h[j], sWon[j], lg);
                cv = fmaf(h[j], sWcv[j], cv);
            }
            float g = (lg > 0.0f) ? cv : 0.0f;   // sigmoid(lg) > 0.5  <=>  lg > 0
            sPrev[tid] = g;
            out[(size_t)(rowbase + tid) * TL + t] = g;
        }
        __syncthreads();
    }
}

extern "C" void kernel_launch(void* const* d_in, const int* in_sizes, int n_in,
                              void* d_out, int out_size) {
    const float* x     = (const float*)d_in[0];
    const int*   tlen  = (const int*)d_in[1];
    const float* eWih0 = (const float*)d_in[2];
    const float* eWhh0 = (const float*)d_in[3];
    const float* ebih0 = (const float*)d_in[4];
    const float* ebhh0 = (const float*)d_in[5];
    const float* eWih1 = (const float*)d_in[6];
    const float* eWhh1 = (const float*)d_in[7];
    const float* ebih1 = (const float*)d_in[8];
    const float* ebhh1 = (const float*)d_in[9];
    const float* dWih0 = (const float*)d_in[10];
    const float* dWhh0 = (const float*)d_in[11];
    const float* dbih0 = (const float*)d_in[12];
    const float* dbhh0 = (const float*)d_in[13];
    const float* dWih1 = (const float*)d_in[14];
    const float* dWhh1 = (const float*)d_in[15];
    const float* dbih1 = (const float*)d_in[16];
    const float* dbhh1 = (const float*)d_in[17];
    const float* Won   = (const float*)d_in[18];
    const float* bon   = (const float*)d_in[19];
    const float* Wcv   = (const float*)d_in[20];
    const float* bcv   = (const float*)d_in[21];
    float* out = (float*)d_out;

    int B = in_sizes[0] / (TENC * NIn);
    int grid = B / ROWS;

    size_t smem = (size_t)SMEM_FLOATS * sizeof(float);
    cudaFuncSetAttribute(ccseq_kernel, cudaFuncAttributeMaxDynamicSharedMemorySize, (int)smem);

    ccseq_kernel<<<grid, NTHR, smem>>>(
        x, tlen,
        eWih0, eWhh0, ebih0, ebhh0, eWih1, eWhh1, ebih1, ebhh1,
        dWih0, dWhh0, dbih0, dbhh0, dWih1, dWhh1, dbih1, dbhh1,
        Won, bon, Wcv, bcv, out);
}

// round 4
// speedup vs baseline: 3.3329x; 3.3329x over previous
#include <cuda_runtime.h>
#include <math.h>

#define NTHR   512
#define ROWS   128
#define HH     64
#define TENC   256
#define NIn    6
#define XSTR   (TENC*NIn)
#define HPS    65     // H pair-row stride in float2/ull units (65 -> conflict-free)
#define XPS    8      // x pair-row stride in float2 units

typedef unsigned long long ull;

// ---- shared layout (float offsets) ----
#define OFF_WHH0 0
#define OFF_WIH1 12288
#define OFF_WHH1 24576
#define OFF_WIH0 36864            // 1152 (encoder [6][192]) / dec vector [192]
#define OFF_B0I  38016
#define OFF_B0H  38208
#define OFF_B1I  38400
#define OFF_B1H  38592
#define OFF_H0   38784            // 64 pairs * 65 * 2 = 8320
#define OFF_H1   47104            // 8320
#define OFF_X0   55424            // 64*8*2 = 1024
#define OFF_X1   56448            // 1024
#define OFF_PREV 57472            // 128 (64 float2)
#define OFF_WON  57600            // 64
#define OFF_WCV  57664            // 64
#define OFF_HB   57728            // 2
#define SMEM_FLOATS 57730

__device__ __forceinline__ ull splat(float v) {
    ull r; asm("mov.b64 %0, {%1, %1};" : "=l"(r) : "f"(v)); return r;
}
__device__ __forceinline__ ull pack2(float a, float b) {
    ull r; asm("mov.b64 %0, {%1, %2};" : "=l"(r) : "f"(a), "f"(b)); return r;
}
__device__ __forceinline__ float2 unp(ull v) {
    float2 f; asm("mov.b64 {%0, %1}, %2;" : "=f"(f.x), "=f"(f.y) : "l"(v)); return f;
}
__device__ __forceinline__ void fma2(ull& d, ull a, ull b) {
    asm("fma.rn.f32x2 %0, %1, %2, %0;" : "+l"(d) : "l"(a), "l"(b));
}

__device__ __forceinline__ float sigf(float x) {
    return __fdividef(1.0f, 1.0f + __expf(-x));
}
__device__ __forceinline__ float tanhfast(float x) {
    float e = __expf(2.0f * x);
    return 1.0f - __fdividef(2.0f, e + 1.0f);
}

// transpose [192][64] gmem -> [64][192] smem
__device__ __forceinline__ void loadWT(float* dst, const float* __restrict__ g) {
    for (int i = threadIdx.x; i < 64 * 192; i += NTHR) {
        int k = i / 192, j = i - k * 192;
        dst[i] = g[j * 64 + k];
    }
}

// Accumulate U[pairs][K] @ W[K][192] into thread tile (4 pairs x 2 units x 3 gates).
// aT receives the "n"-gate partial (aIN for input matmuls, aHN for hidden matmuls).
template <int K, int PSTR>
__device__ __forceinline__ void accumK(const float* __restrict__ W,
                                       const ull* __restrict__ Up,
                                       int p0, int jb,
                                       ull aR[4][2], ull aZ[4][2], ull aT[4][2]) {
    const ull* h = Up + p0 * PSTR;
    const float* w = W + jb;
#pragma unroll 4
    for (int k = 0; k < K; k++) {
        ull h0 = h[k], h1 = h[PSTR + k], h2 = h[2 * PSTR + k], h3 = h[3 * PSTR + k];
        float2 wr = *(const float2*)w;
        float2 wz = *(const float2*)(w + 64);
        float2 wn = *(const float2*)(w + 128);
        ull wr0 = splat(wr.x), wr1 = splat(wr.y);
        ull wz0 = splat(wz.x), wz1 = splat(wz.y);
        ull wn0 = splat(wn.x), wn1 = splat(wn.y);
        fma2(aR[0][0], h0, wr0); fma2(aR[0][1], h0, wr1);
        fma2(aZ[0][0], h0, wz0); fma2(aZ[0][1], h0, wz1);
        fma2(aT[0][0], h0, wn0); fma2(aT[0][1], h0, wn1);
        fma2(aR[1][0], h1, wr0); fma2(aR[1][1], h1, wr1);
        fma2(aZ[1][0], h1, wz0); fma2(aZ[1][1], h1, wz1);
        fma2(aT[1][0], h1, wn0); fma2(aT[1][1], h1, wn1);
        fma2(aR[2][0], h2, wr0); fma2(aR[2][1], h2, wr1);
        fma2(aZ[2][0], h2, wz0); fma2(aZ[2][1], h2, wz1);
        fma2(aT[2][0], h2, wn0); fma2(aT[2][1], h2, wn1);
        fma2(aR[3][0], h3, wr0); fma2(aR[3][1], h3, wr1);
        fma2(aZ[3][0], h3, wz0); fma2(aZ[3][1], h3, wz1);
        fma2(aT[3][0], h3, wn0); fma2(aT[3][1], h3, wn1);
        w += 192;
    }
}

__device__ __forceinline__ void initacc(const float* bi, const float* bh, int jb,
                                        ull aR[4][2], ull aZ[4][2],
                                        ull aIN[4][2], ull aHN[4][2]) {
#pragma unroll
    for (int u = 0; u < 2; u++) {
        ull br  = splat(bi[jb + u] + bh[jb + u]);
        ull bz  = splat(bi[64 + jb + u] + bh[64 + jb + u]);
        ull bin = splat(bi[128 + jb + u]);
        ull bhn = splat(bh[128 + jb + u]);
#pragma unroll
        for (int p = 0; p < 4; p++) {
            aR[p][u] = br; aZ[p][u] = bz; aIN[p][u] = bin; aHN[p][u] = bhn;
        }
    }
}

// compute new h (pair-packed) for the thread tile; no barriers inside
__device__ __forceinline__ void gru_elt(const ull* Hp, int p0, int jb,
                                        ull aR[4][2], ull aZ[4][2],
                                        ull aIN[4][2], ull aHN[4][2],
                                        ull hn[4][2]) {
#pragma unroll
    for (int p = 0; p < 4; p++) {
#pragma unroll
        for (int u = 0; u < 2; u++) {
            float2 rr = unp(aR[p][u]);
            float2 zz = unp(aZ[p][u]);
            float2 ii = unp(aIN[p][u]);
            float2 hh = unp(aHN[p][u]);
            float2 hold = unp(Hp[(p0 + p) * HPS + jb + u]);
            float r0 = sigf(rr.x), r1 = sigf(rr.y);
            float z0 = sigf(zz.x), z1 = sigf(zz.y);
            float n0 = tanhfast(fmaf(r0, hh.x, ii.x));
            float n1 = tanhfast(fmaf(r1, hh.y, ii.y));
            float h0 = fmaf(z0, hold.x - n0, n0);
            float h1 = fmaf(z1, hold.y - n1, n1);
            hn[p][u] = pack2(h0, h1);
        }
    }
}

__device__ __forceinline__ void store_tile(ull* Hp, int p0, int jb, ull hn[4][2]) {
#pragma unroll
    for (int p = 0; p < 4; p++)
#pragma unroll
        for (int u = 0; u < 2; u++)
            Hp[(p0 + p) * HPS + jb + u] = hn[p][u];
}

extern "C" __global__ void __launch_bounds__(NTHR, 1)
ccseq_kernel(const float* __restrict__ x, const int* __restrict__ p_tlen,
             const float* eWih0, const float* eWhh0, const float* ebih0, const float* ebhh0,
             const float* eWih1, const float* eWhh1, const float* ebih1, const float* ebhh1,
             const float* dWih0, const float* dWhh0, const float* dbih0, const float* dbhh0,
             const float* dWih1, const float* dWhh1, const float* dbih1, const float* dbhh1,
             const float* Won, const float* bon, const float* Wcv, const float* bcv,
             float* __restrict__ out) {
    extern __shared__ float sm[];
    float* sWhh0 = sm + OFF_WHH0;
    float* sWih1 = sm + OFF_WIH1;
    float* sWhh1 = sm + OFF_WHH1;
    float* sWih0 = sm + OFF_WIH0;
    float* sB0i  = sm + OFF_B0I;
    float* sB0h  = sm + OFF_B0H;
    float* sB1i  = sm + OFF_B1I;
    float* sB1h  = sm + OFF_B1H;
    ull*   H0u   = (ull*)(sm + OFF_H0);
    ull*   H1u   = (ull*)(sm + OFF_H1);
    ull*   Pv    = (ull*)(sm + OFF_PREV);
    float* sWon  = sm + OFF_WON;
    float* sWcv  = sm + OFF_WCV;
    float* sHb   = sm + OFF_HB;

    const int tid = threadIdx.x;
    const int rowbase = blockIdx.x * ROWS;
    const int ug = tid & 31;
    const int rg = tid >> 5;          // warp id == row-group
    const int jb = ug * 2;            // 2 units per thread
    const int p0 = rg * 4;            // 4 row-pairs (8 rows) per thread

    // ---- encoder weights + biases, zero state, stage x[t=0] ----
    loadWT(sWhh0, eWhh0);
    loadWT(sWih1, eWih1);
    loadWT(sWhh1, eWhh1);
    for (int i = tid; i < NIn * 192; i += NTHR) {
        int k = i / 192, j = i - k * 192;
        sWih0[i] = eWih0[j * NIn + k];
    }
    for (int i = tid; i < 192; i += NTHR) {
        sB0i[i] = ebih0[i]; sB0h[i] = ebhh0[i];
        sB1i[i] = ebih1[i]; sB1h[i] = ebhh1[i];
    }
    for (int i = tid; i < 2 * 8320; i += NTHR) sm[OFF_H0 + i] = 0.0f;
    for (int i = tid; i < ROWS * NIn; i += NTHR) {
        int r = i / NIn, c = i - NIn * r;
        sm[OFF_X0 + ((r >> 1) * XPS + c) * 2 + (r & 1)] =
            x[(size_t)(rowbase + r) * XSTR + c];
    }
    __syncthreads();

    const int TL = p_tlen[0];
    ull aR[4][2], aZ[4][2], aIN[4][2], aHN[4][2], hn[4][2];

    // ================= encoder =================
    for (int t = 0; t < TENC; t++) {
        const ull* Xb = (const ull*)(sm + ((t & 1) ? OFF_X1 : OFF_X0));

        // prefetch x[t+1] to registers
        float xp0 = 0.0f, xp1 = 0.0f;
        if (t + 1 < TENC) {
            int r = tid / NIn, c = tid - NIn * r;
            xp0 = x[(size_t)(rowbase + r) * XSTR + (t + 1) * NIn + c];
            if (tid < 256) {
                int i = tid + NTHR, r2 = i / NIn, c2 = i - NIn * r2;
                xp1 = x[(size_t)(rowbase + r2) * XSTR + (t + 1) * NIn + c2];
            }
        }

        // layer 0
        initacc(sB0i, sB0h, jb, aR, aZ, aIN, aHN);
        accumK<NIn, XPS>(sWih0, Xb, p0, jb, aR, aZ, aIN);
        accumK<HH, HPS>(sWhh0, H0u, p0, jb, aR, aZ, aHN);
        gru_elt(H0u, p0, jb, aR, aZ, aIN, aHN, hn);
        __syncwarp();
        store_tile(H0u, p0, jb, hn);
        __syncwarp();

        // layer 1
        initacc(sB1i, sB1h, jb, aR, aZ, aIN, aHN);
        accumK<HH, HPS>(sWih1, H0u, p0, jb, aR, aZ, aIN);
        accumK<HH, HPS>(sWhh1, H1u, p0, jb, aR, aZ, aHN);
        gru_elt(H1u, p0, jb, aR, aZ, aIN, aHN, hn);
        __syncwarp();
        store_tile(H1u, p0, jb, hn);
        // stage prefetched x into the other buffer (cross-warp; covered by block sync)
        if (t + 1 < TENC) {
            float* xb = sm + (((t + 1) & 1) ? OFF_X1 : OFF_X0);
            int r = tid / NIn, c = tid - NIn * r;
            xb[((r >> 1) * XPS + c) * 2 + (r & 1)] = xp0;
            if (tid < 256) {
                int i = tid + NTHR, r2 = i / NIn, c2 = i - NIn * r2;
                xb[((r2 >> 1) * XPS + c2) * 2 + (r2 & 1)] = xp1;
            }
        }
        __syncthreads();
    }

    // ---- swap in decoder weights ----
    loadWT(sWhh0, dWhh0);
    loadWT(sWih1, dWih1);
    loadWT(sWhh1, dWhh1);
    for (int i = tid; i < 192; i += NTHR) {
        sWih0[i] = dWih0[i];
        sB0i[i] = dbih0[i]; sB0h[i] = dbhh0[i];
        sB1i[i] = dbih1[i]; sB1h[i] = dbhh1[i];
    }
    for (int i = tid; i < HH; i += NTHR) { sWon[i] = Won[i]; sWcv[i] = Wcv[i]; }
    if (tid == 0) { sHb[0] = bon[0]; sHb[1] = bcv[0]; }
    for (int i = tid; i < HH; i += NTHR) Pv[i] = 0ull;
    __syncthreads();

    // ================= decoder =================
    for (int t = 0; t < TL; t++) {
        // layer 0 (K=1 input = prev scalar)
        initacc(sB0i, sB0h, jb, aR, aZ, aIN, aHN);
        {
            ull pv0 = Pv[p0], pv1 = Pv[p0 + 1], pv2 = Pv[p0 + 2], pv3 = Pv[p0 + 3];
#pragma unroll
            for (int u = 0; u < 2; u++) {
                ull wr = splat(sWih0[jb + u]);
                ull wz = splat(sWih0[64 + jb + u]);
                ull wn = splat(sWih0[128 + jb + u]);
                fma2(aR[0][u], pv0, wr); fma2(aZ[0][u], pv0, wz); fma2(aIN[0][u], pv0, wn);
                fma2(aR[1][u], pv1, wr); fma2(aZ[1][u], pv1, wz); fma2(aIN[1][u], pv1, wn);
                fma2(aR[2][u], pv2, wr); fma2(aZ[2][u], pv2, wz); fma2(aIN[2][u], pv2, wn);
                fma2(aR[3][u], pv3, wr); fma2(aZ[3][u], pv3, wz); fma2(aIN[3][u], pv3, wn);
            }
        }
        accumK<HH, HPS>(sWhh0, H0u, p0, jb, aR, aZ, aHN);
        gru_elt(H0u, p0, jb, aR, aZ, aIN, aHN, hn);
        __syncwarp();
        store_tile(H0u, p0, jb, hn);
        __syncwarp();

        // layer 1
        initacc(sB1i, sB1h, jb, aR, aZ, aIN, aHN);
        accumK<HH, HPS>(sWih1, H0u, p0, jb, aR, aZ, aIN);
        accumK<HH, HPS>(sWhh1, H1u, p0, jb, aR, aZ, aHN);
        gru_elt(H1u, p0, jb, aR, aZ, aIN, aHN, hn);
        __syncwarp();
        store_tile(H1u, p0, jb, hn);
        __syncthreads();   // heads read all warps' h1

        // heads
        if (tid < ROWS) {
            const float* hf = ((const float*)H1u) + (tid >> 1) * (2 * HPS) + (tid & 1);
            float lg = sHb[0], cv = sHb[1];
#pragma unroll
            for (int j = 0; j < HH; j++) {
                float hv = hf[2 * j];
                lg = fmaf(hv, sWon[j], lg);
                cv = fmaf(hv, sWcv[j], cv);
            }
            float g = (lg > 0.0f) ? cv : 0.0f;    // sigmoid(lg) > 0.5  <=>  lg > 0
            ((float*)Pv)[tid] = g;
            out[(size_t)(rowbase + tid) * TL + t] = g;
        }
        __syncthreads();   // prev ready for next step
    }
}

extern "C" void kernel_launch(void* const* d_in, const int* in_sizes, int n_in,
                              void* d_out, int out_size) {
    const float* x     = (const float*)d_in[0];
    const int*   tlen  = (const int*)d_in[1];
    const float* eWih0 = (const float*)d_in[2];
    const float* eWhh0 = (const float*)d_in[3];
    const float* ebih0 = (const float*)d_in[4];
    const float* ebhh0 = (const float*)d_in[5];
    const float* eWih1 = (const float*)d_in[6];
    const float* eWhh1 = (const float*)d_in[7];
    const float* ebih1 = (const float*)d_in[8];
    const float* ebhh1 = (const float*)d_in[9];
    const float* dWih0 = (const float*)d_in[10];
    const float* dWhh0 = (const float*)d_in[11];
    const float* dbih0 = (const float*)d_in[12];
    const float* dbhh0 = (const float*)d_in[13];
    const float* dWih1 = (const float*)d_in[14];
    const float* dWhh1 = (const float*)d_in[15];
    const float* dbih1 = (const float*)d_in[16];
    const float* dbhh1 = (const float*)d_in[17];
    const float* Won   = (const float*)d_in[18];
    const float* bon   = (const float*)d_in[19];
    const float* Wcv   = (const float*)d_in[20];
    const float* bcv   = (const float*)d_in[21];
    float* out = (float*)d_out;

    int B = in_sizes[0] / XSTR;
    int grid = B / ROWS;

    size_t smem = (size_t)SMEM_FLOATS * sizeof(float);
    cudaFuncSetAttribute(ccseq_kernel, cudaFuncAttributeMaxDynamicSharedMemorySize, (int)smem);

    ccseq_kernel<<<grid, NTHR, smem>>>(
        x, tlen,
        eWih0, eWhh0, ebih0, ebhh0, eWih1, eWhh1, ebih1, ebhh1,
        dWih0, dWhh0, dbih0, dbhh0, dWih1, dWhh1, dbih1, dbhh1,
        Won, bon, Wcv, bcv, out);
}